// round 12
// baseline (speedup 1.0000x reference)
#include <cuda_runtime.h>

#define NPTS    4096
#define NB      8
#define NIC     8         // i-chunks of 512 queries
#define NJH     32        // j-segments of 128 targets
#define JSEG    128
#define THREADS 128
#define NQ      4         // queries per thread
#define NPART   32        // ic*4 + wid  (128 i's per warp-part)
#define BIAS    128.0f

// stage1 -> stage2 partials (static device arrays: allocation-free)
__device__ float g_colpart[NB * NPART * NPTS];   // [b][part][j], 4 MB
__device__ float g_rowpart[NB * NPTS * NJH];     // [b][i][jh],   4 MB
__device__ float g_final[160];

// ---- packed f32x2 + redux helpers ----
__device__ __forceinline__ double pack2(float lo, float hi) {
    double d; asm("mov.b64 %0, {%1, %2};" : "=d"(d) : "f"(lo), "f"(hi)); return d;
}
__device__ __forceinline__ double fma2(double a, double b, double c) {
    double d; asm("fma.rn.f32x2 %0, %1, %2, %3;" : "=d"(d) : "d"(a), "d"(b), "d"(c)); return d;
}
__device__ __forceinline__ double add2(double a, double b) {
    double d; asm("add.rn.f32x2 %0, %1, %2;" : "=d"(d) : "d"(a), "d"(b)); return d;
}
__device__ __forceinline__ void unpack2(double d, float& lo, float& hi) {
    asm("mov.b64 {%0, %1}, %2;" : "=f"(lo), "=f"(hi) : "d"(d));
}
__device__ __forceinline__ void lds_v2b64(double& a, double& b, unsigned addr) {
    asm volatile("ld.shared.v2.b64 {%0, %1}, [%2];" : "=d"(a), "=d"(b) : "r"(addr));
}
__device__ __forceinline__ unsigned redux_min_u32(unsigned v) {
    unsigned r; asm("redux.sync.min.u32 %0, %1, 0xffffffff;" : "=r"(r) : "r"(v)); return r;
}

// Stage 1: block = (b, i-chunk of 512, j-segment of 128). Each pdist tile is
// computed ONCE, biased positive: d''' = |x_i - y_j|^2 + 128, via
//   d''' = (-2qx)tx + (-2qy)ty + (-2qz)tz + ((t^2+128) + q^2)
// 4 queries/thread amortizes the j-side costs (LDS, col fold, REDUX, STG)
// over 2x more pairs: ~4.9 issue slots/pair vs 5.9 at 2 queries/thread.
// Row mins (over j) accumulate in registers; col mins (over the warp's
// 128 i's) use one redux.sync.min.u32 per (warp, j).
__global__ __launch_bounds__(THREADS, 5)
void chamfer_stage1(const float* __restrict__ x, const float* __restrict__ y) {
    __shared__ __align__(16) float sm[4 * JSEG];   // planes: tx, ty, tz, t^2+BIAS

    const int blk = blockIdx.x;
    const int jh  = blk & 31;
    const int ic  = (blk >> 5) & 7;
    const int b   = blk >> 8;

    const float* __restrict__ q = x + b * NPTS * 3;
    const float* __restrict__ t = y + b * NPTS * 3;
    const int j0 = jh * JSEG;

    if (threadIdx.x < JSEG) {
        const int i = threadIdx.x;
        const float tx = t[(j0 + i) * 3 + 0];
        const float ty = t[(j0 + i) * 3 + 1];
        const float tz = t[(j0 + i) * 3 + 2];
        sm[i] = tx; sm[JSEG + i] = ty; sm[2 * JSEG + i] = tz;
        sm[3 * JSEG + i] = tx * tx + ty * ty + tz * tz + BIAS;
    }
    __syncthreads();

    // 4 queries per thread: i = ic*512 + tid + {0,128,256,384}
    double px[NQ], py[NQ], pz[NQ], ps[NQ];
    int ibase = ic * 512 + threadIdx.x;
#pragma unroll
    for (int qi = 0; qi < NQ; qi++) {
        const int i = ibase + qi * THREADS;
        const float qx = q[i * 3 + 0], qy = q[i * 3 + 1], qz = q[i * 3 + 2];
        px[qi] = pack2(-2.f * qx, -2.f * qx);
        py[qi] = pack2(-2.f * qy, -2.f * qy);
        pz[qi] = pack2(-2.f * qz, -2.f * qz);
        const float qs = qx * qx + qy * qy + qz * qz;
        ps[qi] = pack2(qs, qs);
    }

    float r0[NQ], r1[NQ];
#pragma unroll
    for (int qi = 0; qi < NQ; qi++) { r0[qi] = 1e30f; r1[qi] = 1e30f; }

    const int wid = threadIdx.x >> 5;
    const bool lane0 = (threadIdx.x & 31) == 0;
    float4* __restrict__ colout =
        (float4*)&g_colpart[(b * NPART + ic * 4 + wid) * NPTS + j0];

    unsigned a = (unsigned)__cvta_generic_to_shared(sm);

#pragma unroll 4
    for (int k = 0; k < JSEG / 4; k++, a += 16) {
        double x01, x23, y01, y23, z01, z23, w01, w23;
        lds_v2b64(x01, x23, a);
        lds_v2b64(y01, y23, a + 512u);
        lds_v2b64(z01, z23, a + 1024u);
        lds_v2b64(w01, w23, a + 1536u);

        float f0[NQ], f1[NQ], f2[NQ], f3[NQ];
#pragma unroll
        for (int qi = 0; qi < NQ; qi++) {
            const double t01 = add2(w01, ps[qi]);
            const double t23 = add2(w23, ps[qi]);
            const double d0 =
                fma2(px[qi], x01, fma2(py[qi], y01, fma2(pz[qi], z01, t01)));
            const double d1 =
                fma2(px[qi], x23, fma2(py[qi], y23, fma2(pz[qi], z23, t23)));
            unpack2(d0, f0[qi], f1[qi]);
            unpack2(d1, f2[qi], f3[qi]);
            r0[qi] = fminf(fminf(r0[qi], f0[qi]), f2[qi]);
            r1[qi] = fminf(fminf(r1[qi], f1[qi]), f3[qi]);
        }

        // col fold across the 4 queries, then across the warp's 32 lanes.
        // d''' > 0 so u32-min on the bit pattern == float-min.
        const float c0 = fminf(fminf(f0[0], f0[1]), fminf(f0[2], f0[3]));
        const float c1 = fminf(fminf(f1[0], f1[1]), fminf(f1[2], f1[3]));
        const float c2 = fminf(fminf(f2[0], f2[1]), fminf(f2[2], f2[3]));
        const float c3 = fminf(fminf(f3[0], f3[1]), fminf(f3[2], f3[3]));
        const unsigned u0 = redux_min_u32(__float_as_uint(c0));
        const unsigned u1 = redux_min_u32(__float_as_uint(c1));
        const unsigned u2 = redux_min_u32(__float_as_uint(c2));
        const unsigned u3 = redux_min_u32(__float_as_uint(c3));
        if (lane0)
            colout[k] = make_float4(__uint_as_float(u0), __uint_as_float(u1),
                                    __uint_as_float(u2), __uint_as_float(u3));
    }

#pragma unroll
    for (int qi = 0; qi < NQ; qi++) {
        const int i = ibase + qi * THREADS;
        g_rowpart[(b * NPTS + i) * NJH + jh] = fminf(r0[qi], r1[qi]);
    }
}

__device__ __forceinline__ void block_sum_to(float local, int slot) {
    __shared__ float red[8];
#pragma unroll
    for (int o = 16; o; o >>= 1) local += __shfl_down_sync(0xFFFFFFFFu, local, o);
    if ((threadIdx.x & 31) == 0) red[threadIdx.x >> 5] = local;
    __syncthreads();
    if (threadIdx.x == 0) {
        float s = ((red[0] + red[1]) + (red[2] + red[3]))
                + ((red[4] + red[5]) + (red[6] + red[7]));
        g_final[slot] = s;
    }
}

// Stage 2: blocks 0..127 = col side (b, j-slice of 256): min over 32 parts,
// unbias, sum. Blocks 128..143 = row side (b, i-half): min over 32 jh, sum.
__global__ __launch_bounds__(256)
void chamfer_stage2() {
    float local = 0.f;
    if (blockIdx.x < 128) {
        const int b = blockIdx.x >> 4;
        const int j = (blockIdx.x & 15) * 256 + threadIdx.x;
        float m0 = 1e30f;
        const float* base = &g_colpart[b * NPART * NPTS];
#pragma unroll 8
        for (int p = 0; p < NPART; p++)
            m0 = fminf(m0, base[p * NPTS + j]);
        local = m0 - BIAS;
    } else {
        const int blk2 = blockIdx.x - 128;   // 0..15
        const int b = blk2 >> 1;
        const int ibase = (blk2 & 1) * 2048;
        for (int i = ibase + threadIdx.x; i < ibase + 2048; i += 256) {
            const float4* r = (const float4*)&g_rowpart[(b * NPTS + i) * NJH];
            float m = 1e30f;
#pragma unroll
            for (int v = 0; v < 8; v++) {
                const float4 w = r[v];
                m = fminf(m, fminf(fminf(w.x, w.y), fminf(w.z, w.w)));
            }
            local += m - BIAS;
        }
    }
    block_sum_to(local, blockIdx.x);
}

// Stage 3: sum the 144 partials, scale: loss = sum * 0.005 / 32768
__global__ void chamfer_stage3(float* __restrict__ out) {
    __shared__ float red[5];
    float v = (threadIdx.x < 144) ? g_final[threadIdx.x] : 0.f;
#pragma unroll
    for (int o = 16; o; o >>= 1) v += __shfl_down_sync(0xFFFFFFFFu, v, o);
    if ((threadIdx.x & 31) == 0) red[threadIdx.x >> 5] = v;
    __syncthreads();
    if (threadIdx.x == 0) {
        float s = (((red[0] + red[1]) + (red[2] + red[3])) + red[4]);
        out[0] = s * (0.005f / 32768.f);
    }
}

extern "C" void kernel_launch(void* const* d_in, const int* in_sizes, int n_in,
                              void* d_out, int out_size) {
    const float* x = (const float*)d_in[0];
    const float* y = (const float*)d_in[1];
    float* out = (float*)d_out;
    chamfer_stage1<<<NB * NIC * NJH, THREADS>>>(x, y);
    chamfer_stage2<<<144, 256>>>();
    chamfer_stage3<<<1, 160>>>(out);
}

// round 13
// speedup vs baseline: 1.1031x; 1.1031x over previous
#include <cuda_runtime.h>

#define NPTS    4096
#define NB      8
#define NIC     8         // i-chunks of 512 queries
#define NJH     32        // j-segments of 128 targets
#define JSEG    128
#define THREADS 128
#define NQ      4         // queries per thread
#define NPART   32        // ic*4 + wid  (128 i's per warp-part)
#define BIAS    128.0f

// stage1 -> stage2 partials (static device arrays: allocation-free)
__device__ float g_colpart[NB * NPART * NPTS];   // [b][part][j], 4 MB
__device__ float g_rowpart[NB * NPTS * NJH];     // [b][i][jh],   4 MB
__device__ float g_final[192];

// ---- packed f32x2 + redux helpers ----
__device__ __forceinline__ double pack2(float lo, float hi) {
    double d; asm("mov.b64 %0, {%1, %2};" : "=d"(d) : "f"(lo), "f"(hi)); return d;
}
__device__ __forceinline__ double fma2(double a, double b, double c) {
    double d; asm("fma.rn.f32x2 %0, %1, %2, %3;" : "=d"(d) : "d"(a), "d"(b), "d"(c)); return d;
}
__device__ __forceinline__ double add2(double a, double b) {
    double d; asm("add.rn.f32x2 %0, %1, %2;" : "=d"(d) : "d"(a), "d"(b)); return d;
}
__device__ __forceinline__ void unpack2(double d, float& lo, float& hi) {
    asm("mov.b64 {%0, %1}, %2;" : "=f"(lo), "=f"(hi) : "d"(d));
}
__device__ __forceinline__ void lds_v2b64(double& a, double& b, unsigned addr) {
    asm volatile("ld.shared.v2.b64 {%0, %1}, [%2];" : "=d"(a), "=d"(b) : "r"(addr));
}
__device__ __forceinline__ unsigned redux_min_u32(unsigned v) {
    unsigned r; asm("redux.sync.min.u32 %0, %1, 0xffffffff;" : "=r"(r) : "r"(v)); return r;
}

// Stage 1 (unchanged from R12 — measured 30.8us): block = (b, i-chunk of 512,
// j-segment of 128). d''' = |x_i - y_j|^2 + 128 computed once per pair via
//   d''' = (-2qx)tx + (-2qy)ty + (-2qz)tz + ((t^2+128) + q^2)
// 4 queries/thread amortizes j-side costs (LDS, col fold, REDUX, STG).
__global__ __launch_bounds__(THREADS, 5)
void chamfer_stage1(const float* __restrict__ x, const float* __restrict__ y) {
    __shared__ __align__(16) float sm[4 * JSEG];   // planes: tx, ty, tz, t^2+BIAS

    const int blk = blockIdx.x;
    const int jh  = blk & 31;
    const int ic  = (blk >> 5) & 7;
    const int b   = blk >> 8;

    const float* __restrict__ q = x + b * NPTS * 3;
    const float* __restrict__ t = y + b * NPTS * 3;
    const int j0 = jh * JSEG;

    if (threadIdx.x < JSEG) {
        const int i = threadIdx.x;
        const float tx = t[(j0 + i) * 3 + 0];
        const float ty = t[(j0 + i) * 3 + 1];
        const float tz = t[(j0 + i) * 3 + 2];
        sm[i] = tx; sm[JSEG + i] = ty; sm[2 * JSEG + i] = tz;
        sm[3 * JSEG + i] = tx * tx + ty * ty + tz * tz + BIAS;
    }
    __syncthreads();

    // 4 queries per thread: i = ic*512 + tid + {0,128,256,384}
    double px[NQ], py[NQ], pz[NQ], ps[NQ];
    int ibase = ic * 512 + threadIdx.x;
#pragma unroll
    for (int qi = 0; qi < NQ; qi++) {
        const int i = ibase + qi * THREADS;
        const float qx = q[i * 3 + 0], qy = q[i * 3 + 1], qz = q[i * 3 + 2];
        px[qi] = pack2(-2.f * qx, -2.f * qx);
        py[qi] = pack2(-2.f * qy, -2.f * qy);
        pz[qi] = pack2(-2.f * qz, -2.f * qz);
        const float qs = qx * qx + qy * qy + qz * qz;
        ps[qi] = pack2(qs, qs);
    }

    float r0[NQ], r1[NQ];
#pragma unroll
    for (int qi = 0; qi < NQ; qi++) { r0[qi] = 1e30f; r1[qi] = 1e30f; }

    const int wid = threadIdx.x >> 5;
    const bool lane0 = (threadIdx.x & 31) == 0;
    float4* __restrict__ colout =
        (float4*)&g_colpart[(b * NPART + ic * 4 + wid) * NPTS + j0];

    unsigned a = (unsigned)__cvta_generic_to_shared(sm);

#pragma unroll 4
    for (int k = 0; k < JSEG / 4; k++, a += 16) {
        double x01, x23, y01, y23, z01, z23, w01, w23;
        lds_v2b64(x01, x23, a);
        lds_v2b64(y01, y23, a + 512u);
        lds_v2b64(z01, z23, a + 1024u);
        lds_v2b64(w01, w23, a + 1536u);

        float f0[NQ], f1[NQ], f2[NQ], f3[NQ];
#pragma unroll
        for (int qi = 0; qi < NQ; qi++) {
            const double t01 = add2(w01, ps[qi]);
            const double t23 = add2(w23, ps[qi]);
            const double d0 =
                fma2(px[qi], x01, fma2(py[qi], y01, fma2(pz[qi], z01, t01)));
            const double d1 =
                fma2(px[qi], x23, fma2(py[qi], y23, fma2(pz[qi], z23, t23)));
            unpack2(d0, f0[qi], f1[qi]);
            unpack2(d1, f2[qi], f3[qi]);
            r0[qi] = fminf(fminf(r0[qi], f0[qi]), f2[qi]);
            r1[qi] = fminf(fminf(r1[qi], f1[qi]), f3[qi]);
        }

        // col fold across the 4 queries, then across the warp's 32 lanes.
        // d''' > 0 so u32-min on the bit pattern == float-min.
        const float c0 = fminf(fminf(f0[0], f0[1]), fminf(f0[2], f0[3]));
        const float c1 = fminf(fminf(f1[0], f1[1]), fminf(f1[2], f1[3]));
        const float c2 = fminf(fminf(f2[0], f2[1]), fminf(f2[2], f2[3]));
        const float c3 = fminf(fminf(f3[0], f3[1]), fminf(f3[2], f3[3]));
        const unsigned u0 = redux_min_u32(__float_as_uint(c0));
        const unsigned u1 = redux_min_u32(__float_as_uint(c1));
        const unsigned u2 = redux_min_u32(__float_as_uint(c2));
        const unsigned u3 = redux_min_u32(__float_as_uint(c3));
        if (lane0)
            colout[k] = make_float4(__uint_as_float(u0), __uint_as_float(u1),
                                    __uint_as_float(u2), __uint_as_float(u3));
    }

#pragma unroll
    for (int qi = 0; qi < NQ; qi++) {
        const int i = ibase + qi * THREADS;
        g_rowpart[(b * NPTS + i) * NJH + jh] = fminf(r0[qi], r1[qi]);
    }
}

__device__ __forceinline__ void block_sum_to(float local, int slot) {
    __shared__ float red[8];
#pragma unroll
    for (int o = 16; o; o >>= 1) local += __shfl_down_sync(0xFFFFFFFFu, local, o);
    if ((threadIdx.x & 31) == 0) red[threadIdx.x >> 5] = local;
    __syncthreads();
    if (threadIdx.x == 0) {
        float s = ((red[0] + red[1]) + (red[2] + red[3]))
                + ((red[4] + red[5]) + (red[6] + red[7]));
        g_final[slot] = s;
    }
}

// Stage 2: blocks 0..127 = col side (b, j-slice of 256): min over 32 parts.
// Blocks 128..191 = row side (b, i-eighth of 512): min over 32 jh.
// Row side widened 16 -> 64 blocks: the 4 MB rowpart read was parallelism-
// starved at 16 blocks (cause of the R12 total regression).
__global__ __launch_bounds__(256)
void chamfer_stage2() {
    float local = 0.f;
    if (blockIdx.x < 128) {
        const int b = blockIdx.x >> 4;
        const int j = (blockIdx.x & 15) * 256 + threadIdx.x;
        float m0 = 1e30f;
        const float* base = &g_colpart[b * NPART * NPTS];
#pragma unroll 8
        for (int p = 0; p < NPART; p++)
            m0 = fminf(m0, base[p * NPTS + j]);
        local = m0 - BIAS;
    } else {
        const int blk2 = blockIdx.x - 128;   // 0..63
        const int b = blk2 >> 3;
        const int ibase = (blk2 & 7) * 512;
#pragma unroll
        for (int ii = 0; ii < 2; ii++) {
            const int i = ibase + ii * 256 + threadIdx.x;
            const float4* r = (const float4*)&g_rowpart[(b * NPTS + i) * NJH];
            float m = 1e30f;
#pragma unroll
            for (int v = 0; v < 8; v++) {
                const float4 w = r[v];
                m = fminf(m, fminf(fminf(w.x, w.y), fminf(w.z, w.w)));
            }
            local += m - BIAS;
        }
    }
    block_sum_to(local, blockIdx.x);
}

// Stage 3: sum the 192 partials, scale: loss = sum * 0.005 / 32768
__global__ void chamfer_stage3(float* __restrict__ out) {
    __shared__ float red[6];
    float v = (threadIdx.x < 192) ? g_final[threadIdx.x] : 0.f;
#pragma unroll
    for (int o = 16; o; o >>= 1) v += __shfl_down_sync(0xFFFFFFFFu, v, o);
    if ((threadIdx.x & 31) == 0) red[threadIdx.x >> 5] = v;
    __syncthreads();
    if (threadIdx.x == 0) {
        float s = ((red[0] + red[1]) + (red[2] + red[3])) + (red[4] + red[5]);
        out[0] = s * (0.005f / 32768.f);
    }
}

extern "C" void kernel_launch(void* const* d_in, const int* in_sizes, int n_in,
                              void* d_out, int out_size) {
    const float* x = (const float*)d_in[0];
    const float* y = (const float*)d_in[1];
    float* out = (float*)d_out;
    chamfer_stage1<<<NB * NIC * NJH, THREADS>>>(x, y);
    chamfer_stage2<<<192, 256>>>();
    chamfer_stage3<<<1, 192>>>(out);
}

// round 14
// speedup vs baseline: 1.2254x; 1.1109x over previous
#include <cuda_runtime.h>

#define NPTS    4096
#define NB      8
#define NIC     8         // i-chunks of 512 queries
#define NJH     32        // j-segments of 128 targets
#define JSEG    128
#define THREADS 128
#define NQ      4         // queries per thread
#define BIAS    128.0f
#define FMAXB   0x7f7fffffu   // FLT_MAX bits: init value for u32 float-min

// global min accumulators (u32 bit-pattern mins; deterministic) + partials
__device__ unsigned g_colmin[NB * NPTS];   // [b][j], 128 KB
__device__ unsigned g_rowmin[NB * NPTS];   // [b][i], 128 KB
__device__ float g_final[64];

// ---- packed f32x2 + redux helpers ----
__device__ __forceinline__ double pack2(float lo, float hi) {
    double d; asm("mov.b64 %0, {%1, %2};" : "=d"(d) : "f"(lo), "f"(hi)); return d;
}
__device__ __forceinline__ double fma2(double a, double b, double c) {
    double d; asm("fma.rn.f32x2 %0, %1, %2, %3;" : "=d"(d) : "d"(a), "d"(b), "d"(c)); return d;
}
__device__ __forceinline__ double add2(double a, double b) {
    double d; asm("add.rn.f32x2 %0, %1, %2;" : "=d"(d) : "d"(a), "d"(b)); return d;
}
__device__ __forceinline__ void unpack2(double d, float& lo, float& hi) {
    asm("mov.b64 {%0, %1}, %2;" : "=f"(lo), "=f"(hi) : "d"(d));
}
__device__ __forceinline__ void lds_v2b64(double& a, double& b, unsigned addr) {
    asm volatile("ld.shared.v2.b64 {%0, %1}, [%2];" : "=d"(a), "=d"(b) : "r"(addr));
}
__device__ __forceinline__ unsigned redux_min_u32(unsigned v) {
    unsigned r; asm("redux.sync.min.u32 %0, %1, 0xffffffff;" : "=r"(r) : "r"(v)); return r;
}

// Stage 0: init the min accumulators to FLT_MAX bits (fresh every call)
__global__ void chamfer_init() {
    const int i = blockIdx.x * 1024 + threadIdx.x;
    uint4 v = make_uint4(FMAXB, FMAXB, FMAXB, FMAXB);
    ((uint4*)g_colmin)[i] = v;
    ((uint4*)g_rowmin)[i] = v;
}

// Stage 1 (hot loop identical to R12/R13 — measured 30.1us): block =
// (b, i-chunk of 512, j-segment of 128).
//   d''' = (-2qx)tx + (-2qy)ty + (-2qz)tz + ((t^2+128) + q^2)  ( > 0 )
// Col mins buffer in SMEM per warp, fold across warps post-loop, then ONE
// u32 atomicMin per (block, j). Row mins: 4 atomicMin per thread post-loop.
// u32 min on positive-float bit patterns == float min; atomic min is
// order-independent -> deterministic.
__global__ __launch_bounds__(THREADS, 5)
void chamfer_stage1(const float* __restrict__ x, const float* __restrict__ y) {
    __shared__ __align__(16) float sm[4 * JSEG];    // tx, ty, tz, t^2+BIAS
    __shared__ __align__(16) float scol[4 * JSEG];  // per-warp col mins

    const int blk = blockIdx.x;
    const int jh  = blk & 31;
    const int ic  = (blk >> 5) & 7;
    const int b   = blk >> 8;

    const float* __restrict__ q = x + b * NPTS * 3;
    const float* __restrict__ t = y + b * NPTS * 3;
    const int j0 = jh * JSEG;

    if (threadIdx.x < JSEG) {
        const int i = threadIdx.x;
        const float tx = t[(j0 + i) * 3 + 0];
        const float ty = t[(j0 + i) * 3 + 1];
        const float tz = t[(j0 + i) * 3 + 2];
        sm[i] = tx; sm[JSEG + i] = ty; sm[2 * JSEG + i] = tz;
        sm[3 * JSEG + i] = tx * tx + ty * ty + tz * tz + BIAS;
    }
    __syncthreads();

    // 4 queries per thread: i = ic*512 + tid + {0,128,256,384}
    double px[NQ], py[NQ], pz[NQ], ps[NQ];
    int ibase = ic * 512 + threadIdx.x;
#pragma unroll
    for (int qi = 0; qi < NQ; qi++) {
        const int i = ibase + qi * THREADS;
        const float qx = q[i * 3 + 0], qy = q[i * 3 + 1], qz = q[i * 3 + 2];
        px[qi] = pack2(-2.f * qx, -2.f * qx);
        py[qi] = pack2(-2.f * qy, -2.f * qy);
        pz[qi] = pack2(-2.f * qz, -2.f * qz);
        const float qs = qx * qx + qy * qy + qz * qz;
        ps[qi] = pack2(qs, qs);
    }

    float r0[NQ], r1[NQ];
#pragma unroll
    for (int qi = 0; qi < NQ; qi++) { r0[qi] = 1e30f; r1[qi] = 1e30f; }

    const int wid = threadIdx.x >> 5;
    const bool lane0 = (threadIdx.x & 31) == 0;
    float4* __restrict__ colbuf = (float4*)&scol[wid * JSEG];

    unsigned a = (unsigned)__cvta_generic_to_shared(sm);

#pragma unroll 4
    for (int k = 0; k < JSEG / 4; k++, a += 16) {
        double x01, x23, y01, y23, z01, z23, w01, w23;
        lds_v2b64(x01, x23, a);
        lds_v2b64(y01, y23, a + 512u);
        lds_v2b64(z01, z23, a + 1024u);
        lds_v2b64(w01, w23, a + 1536u);

        float f0[NQ], f1[NQ], f2[NQ], f3[NQ];
#pragma unroll
        for (int qi = 0; qi < NQ; qi++) {
            const double t01 = add2(w01, ps[qi]);
            const double t23 = add2(w23, ps[qi]);
            const double d0 =
                fma2(px[qi], x01, fma2(py[qi], y01, fma2(pz[qi], z01, t01)));
            const double d1 =
                fma2(px[qi], x23, fma2(py[qi], y23, fma2(pz[qi], z23, t23)));
            unpack2(d0, f0[qi], f1[qi]);
            unpack2(d1, f2[qi], f3[qi]);
            r0[qi] = fminf(fminf(r0[qi], f0[qi]), f2[qi]);
            r1[qi] = fminf(fminf(r1[qi], f1[qi]), f3[qi]);
        }

        // col fold across the 4 queries, then across the warp's 32 lanes
        const float c0 = fminf(fminf(f0[0], f0[1]), fminf(f0[2], f0[3]));
        const float c1 = fminf(fminf(f1[0], f1[1]), fminf(f1[2], f1[3]));
        const float c2 = fminf(fminf(f2[0], f2[1]), fminf(f2[2], f2[3]));
        const float c3 = fminf(fminf(f3[0], f3[1]), fminf(f3[2], f3[3]));
        const unsigned u0 = redux_min_u32(__float_as_uint(c0));
        const unsigned u1 = redux_min_u32(__float_as_uint(c1));
        const unsigned u2 = redux_min_u32(__float_as_uint(c2));
        const unsigned u3 = redux_min_u32(__float_as_uint(c3));
        if (lane0)
            colbuf[k] = make_float4(__uint_as_float(u0), __uint_as_float(u1),
                                    __uint_as_float(u2), __uint_as_float(u3));
    }

    // row mins -> global atomic min (order-independent, exact)
#pragma unroll
    for (int qi = 0; qi < NQ; qi++) {
        const int i = ibase + qi * THREADS;
        atomicMin(&g_rowmin[b * NPTS + i],
                  __float_as_uint(fminf(r0[qi], r1[qi])));
    }

    // fold 4 warp-col buffers and issue one atomic min per j
    __syncthreads();
    {
        const int j = threadIdx.x;           // 0..127
        const float m = fminf(fminf(scol[j], scol[JSEG + j]),
                              fminf(scol[2 * JSEG + j], scol[3 * JSEG + j]));
        atomicMin(&g_colmin[b * NPTS + j0 + j], __float_as_uint(m));
    }
}

// Stage 2: sum the 64K mins (both sides), unbias. 64 blocks x 256 threads,
// each thread handles 4 contiguous values via one uint4 load.
__global__ __launch_bounds__(256)
void chamfer_stage2() {
    const unsigned* src = (blockIdx.x < 32) ? g_colmin : g_rowmin;
    const int seg = (blockIdx.x & 31);
    const uint4 v = ((const uint4*)src)[seg * 256 + threadIdx.x];
    float local = (__uint_as_float(v.x) - BIAS) + (__uint_as_float(v.y) - BIAS)
                + (__uint_as_float(v.z) - BIAS) + (__uint_as_float(v.w) - BIAS);
    __shared__ float red[8];
#pragma unroll
    for (int o = 16; o; o >>= 1) local += __shfl_down_sync(0xFFFFFFFFu, local, o);
    if ((threadIdx.x & 31) == 0) red[threadIdx.x >> 5] = local;
    __syncthreads();
    if (threadIdx.x == 0) {
        float s = ((red[0] + red[1]) + (red[2] + red[3]))
                + ((red[4] + red[5]) + (red[6] + red[7]));
        g_final[blockIdx.x] = s;
    }
}

// Stage 3: sum the 64 partials, scale: loss = sum * 0.005 / 32768
__global__ void chamfer_stage3(float* __restrict__ out) {
    __shared__ float red[2];
    float v = g_final[threadIdx.x];
#pragma unroll
    for (int o = 16; o; o >>= 1) v += __shfl_down_sync(0xFFFFFFFFu, v, o);
    if ((threadIdx.x & 31) == 0) red[threadIdx.x >> 5] = v;
    __syncthreads();
    if (threadIdx.x == 0)
        out[0] = (red[0] + red[1]) * (0.005f / 32768.f);
}

extern "C" void kernel_launch(void* const* d_in, const int* in_sizes, int n_in,
                              void* d_out, int out_size) {
    const float* x = (const float*)d_in[0];
    const float* y = (const float*)d_in[1];
    float* out = (float*)d_out;
    chamfer_init<<<8, 1024>>>();
    chamfer_stage1<<<NB * NIC * NJH, THREADS>>>(x, y);
    chamfer_stage2<<<64, 256>>>();
    chamfer_stage3<<<1, 64>>>(out);
}

// round 15
// speedup vs baseline: 1.2618x; 1.0297x over previous
#include <cuda_runtime.h>

#define NPTS    4096
#define NB      8
#define NIC     8         // i-chunks of 512 queries
#define NJH     32        // j-segments of 128 targets
#define JSEG    128
#define THREADS 128
#define NQ      4         // queries per thread
#define BIAS    128.0f
#define FMAXB   0x7f7fffffu   // FLT_MAX bits: init value for u32 float-min
#define SCALE   16777216.0    // 2^24 fixed-point for deterministic integer sum

// global min accumulators (u32 bit-pattern mins; deterministic)
__device__ unsigned g_colmin[NB * NPTS];   // [b][j], 128 KB
__device__ unsigned g_rowmin[NB * NPTS];   // [b][i], 128 KB
__device__ unsigned long long g_acc;       // fixed-point total (associative)
__device__ unsigned g_ticket;

// ---- packed f32x2 + redux helpers ----
__device__ __forceinline__ double pack2(float lo, float hi) {
    double d; asm("mov.b64 %0, {%1, %2};" : "=d"(d) : "f"(lo), "f"(hi)); return d;
}
__device__ __forceinline__ double fma2(double a, double b, double c) {
    double d; asm("fma.rn.f32x2 %0, %1, %2, %3;" : "=d"(d) : "d"(a), "d"(b), "d"(c)); return d;
}
__device__ __forceinline__ double add2(double a, double b) {
    double d; asm("add.rn.f32x2 %0, %1, %2;" : "=d"(d) : "d"(a), "d"(b)); return d;
}
__device__ __forceinline__ void unpack2(double d, float& lo, float& hi) {
    asm("mov.b64 {%0, %1}, %2;" : "=f"(lo), "=f"(hi) : "d"(d));
}
__device__ __forceinline__ void lds_v2b64(double& a, double& b, unsigned addr) {
    asm volatile("ld.shared.v2.b64 {%0, %1}, [%2];" : "=d"(a), "=d"(b) : "r"(addr));
}
__device__ __forceinline__ unsigned redux_min_u32(unsigned v) {
    unsigned r; asm("redux.sync.min.u32 %0, %1, 0xffffffff;" : "=r"(r) : "r"(v)); return r;
}

// Stage 0: init min accumulators to FLT_MAX bits + zero the sum/ticket
__global__ void chamfer_init() {
    const int i = blockIdx.x * 256 + threadIdx.x;    // 32*256 = 8192 uint4s
    uint4 v = make_uint4(FMAXB, FMAXB, FMAXB, FMAXB);
    ((uint4*)g_colmin)[i] = v;
    ((uint4*)g_rowmin)[i] = v;
    if (i == 0) { g_acc = 0ULL; g_ticket = 0u; }
}

// Stage 1 (hot loop identical to R13/R14 — measured 30.1us): block =
// (b, i-chunk of 512, j-segment of 128).
//   d''' = (-2qx)tx + (-2qy)ty + (-2qz)tz + ((t^2+128) + q^2)  ( > 0 )
// Col mins buffer in SMEM per warp, fold across warps post-loop, then ONE
// u32 atomicMin per (block, j). Row mins: 4 atomicMin per thread post-loop.
// u32 min on positive-float bit patterns == float min; min is
// order-independent -> deterministic.
__global__ __launch_bounds__(THREADS, 5)
void chamfer_stage1(const float* __restrict__ x, const float* __restrict__ y) {
    __shared__ __align__(16) float sm[4 * JSEG];    // tx, ty, tz, t^2+BIAS
    __shared__ __align__(16) float scol[4 * JSEG];  // per-warp col mins

    const int blk = blockIdx.x;
    const int jh  = blk & 31;
    const int ic  = (blk >> 5) & 7;
    const int b   = blk >> 8;

    const float* __restrict__ q = x + b * NPTS * 3;
    const float* __restrict__ t = y + b * NPTS * 3;
    const int j0 = jh * JSEG;

    if (threadIdx.x < JSEG) {
        const int i = threadIdx.x;
        const float tx = t[(j0 + i) * 3 + 0];
        const float ty = t[(j0 + i) * 3 + 1];
        const float tz = t[(j0 + i) * 3 + 2];
        sm[i] = tx; sm[JSEG + i] = ty; sm[2 * JSEG + i] = tz;
        sm[3 * JSEG + i] = tx * tx + ty * ty + tz * tz + BIAS;
    }
    __syncthreads();

    // 4 queries per thread: i = ic*512 + tid + {0,128,256,384}
    double px[NQ], py[NQ], pz[NQ], ps[NQ];
    int ibase = ic * 512 + threadIdx.x;
#pragma unroll
    for (int qi = 0; qi < NQ; qi++) {
        const int i = ibase + qi * THREADS;
        const float qx = q[i * 3 + 0], qy = q[i * 3 + 1], qz = q[i * 3 + 2];
        px[qi] = pack2(-2.f * qx, -2.f * qx);
        py[qi] = pack2(-2.f * qy, -2.f * qy);
        pz[qi] = pack2(-2.f * qz, -2.f * qz);
        const float qs = qx * qx + qy * qy + qz * qz;
        ps[qi] = pack2(qs, qs);
    }

    float r0[NQ], r1[NQ];
#pragma unroll
    for (int qi = 0; qi < NQ; qi++) { r0[qi] = 1e30f; r1[qi] = 1e30f; }

    const int wid = threadIdx.x >> 5;
    const bool lane0 = (threadIdx.x & 31) == 0;
    float4* __restrict__ colbuf = (float4*)&scol[wid * JSEG];

    unsigned a = (unsigned)__cvta_generic_to_shared(sm);

#pragma unroll 4
    for (int k = 0; k < JSEG / 4; k++, a += 16) {
        double x01, x23, y01, y23, z01, z23, w01, w23;
        lds_v2b64(x01, x23, a);
        lds_v2b64(y01, y23, a + 512u);
        lds_v2b64(z01, z23, a + 1024u);
        lds_v2b64(w01, w23, a + 1536u);

        float f0[NQ], f1[NQ], f2[NQ], f3[NQ];
#pragma unroll
        for (int qi = 0; qi < NQ; qi++) {
            const double t01 = add2(w01, ps[qi]);
            const double t23 = add2(w23, ps[qi]);
            const double d0 =
                fma2(px[qi], x01, fma2(py[qi], y01, fma2(pz[qi], z01, t01)));
            const double d1 =
                fma2(px[qi], x23, fma2(py[qi], y23, fma2(pz[qi], z23, t23)));
            unpack2(d0, f0[qi], f1[qi]);
            unpack2(d1, f2[qi], f3[qi]);
            r0[qi] = fminf(fminf(r0[qi], f0[qi]), f2[qi]);
            r1[qi] = fminf(fminf(r1[qi], f1[qi]), f3[qi]);
        }

        // col fold across the 4 queries, then across the warp's 32 lanes
        const float c0 = fminf(fminf(f0[0], f0[1]), fminf(f0[2], f0[3]));
        const float c1 = fminf(fminf(f1[0], f1[1]), fminf(f1[2], f1[3]));
        const float c2 = fminf(fminf(f2[0], f2[1]), fminf(f2[2], f2[3]));
        const float c3 = fminf(fminf(f3[0], f3[1]), fminf(f3[2], f3[3]));
        const unsigned u0 = redux_min_u32(__float_as_uint(c0));
        const unsigned u1 = redux_min_u32(__float_as_uint(c1));
        const unsigned u2 = redux_min_u32(__float_as_uint(c2));
        const unsigned u3 = redux_min_u32(__float_as_uint(c3));
        if (lane0)
            colbuf[k] = make_float4(__uint_as_float(u0), __uint_as_float(u1),
                                    __uint_as_float(u2), __uint_as_float(u3));
    }

    // row mins -> global atomic min (order-independent, exact)
#pragma unroll
    for (int qi = 0; qi < NQ; qi++) {
        const int i = ibase + qi * THREADS;
        atomicMin(&g_rowmin[b * NPTS + i],
                  __float_as_uint(fminf(r0[qi], r1[qi])));
    }

    // fold 4 warp-col buffers and issue one atomic min per j
    __syncthreads();
    {
        const int j = threadIdx.x;           // 0..127
        const float m = fminf(fminf(scol[j], scol[JSEG + j]),
                              fminf(scol[2 * JSEG + j], scol[3 * JSEG + j]));
        atomicMin(&g_colmin[b * NPTS + j0 + j], __float_as_uint(m));
    }
}

// Stage 2: 64 blocks sum the 64K mins (both sides), unbias, and accumulate
// into a fixed-point u64 (integer add = associative = deterministic). The
// last block to finish converts and writes the final scalar — no stage 3.
__global__ __launch_bounds__(256)
void chamfer_stage2(float* __restrict__ out) {
    const unsigned* src = (blockIdx.x < 32) ? g_colmin : g_rowmin;
    const int seg = (blockIdx.x & 31);
    const uint4 v = ((const uint4*)src)[seg * 256 + threadIdx.x];
    float local = (__uint_as_float(v.x) - BIAS) + (__uint_as_float(v.y) - BIAS)
                + (__uint_as_float(v.z) - BIAS) + (__uint_as_float(v.w) - BIAS);
    __shared__ float red[8];
#pragma unroll
    for (int o = 16; o; o >>= 1) local += __shfl_down_sync(0xFFFFFFFFu, local, o);
    if ((threadIdx.x & 31) == 0) red[threadIdx.x >> 5] = local;
    __syncthreads();
    if (threadIdx.x == 0) {
        const float s = ((red[0] + red[1]) + (red[2] + red[3]))
                      + ((red[4] + red[5]) + (red[6] + red[7]));
        atomicAdd(&g_acc, (unsigned long long)((double)s * SCALE + 0.5));
        __threadfence();
        const unsigned t = atomicAdd(&g_ticket, 1u);
        if (t == 63u) {
            const unsigned long long acc = atomicAdd(&g_acc, 0ULL);
            out[0] = (float)((double)acc * (1.0 / SCALE) * (0.005 / 32768.0));
        }
    }
}

extern "C" void kernel_launch(void* const* d_in, const int* in_sizes, int n_in,
                              void* d_out, int out_size) {
    const float* x = (const float*)d_in[0];
    const float* y = (const float*)d_in[1];
    float* out = (float*)d_out;
    chamfer_init<<<32, 256>>>();
    chamfer_stage1<<<NB * NIC * NJH, THREADS>>>(x, y);
    chamfer_stage2<<<64, 256>>>(out);
}

// round 16
// speedup vs baseline: 1.2980x; 1.0287x over previous
#include <cuda_runtime.h>

#define NPTS    4096
#define NB      8
#define NIC     8         // i-chunks of 512 queries
#define NJH     32        // j-segments of 128 targets
#define JSEG    128
#define THREADS 128
#define NQ      4         // queries per thread
#define BIAS    128.0f
#define SCALE   16777216.0    // 2^24 fixed-point for deterministic integer sum

// Min accumulators hold COMPLEMENTED float bits: float-min == u32-max of ~bits.
// Natural init is 0 (CUDA zero-inits device globals); stage2 re-zeros after
// reading so every kernel_launch invocation starts from identical state.
__device__ unsigned g_colmin[NB * NPTS];   // [b][j], 128 KB
__device__ unsigned g_rowmin[NB * NPTS];   // [b][i], 128 KB
__device__ unsigned long long g_acc;       // fixed-point total (associative)
__device__ unsigned g_ticket;

// ---- packed f32x2 + redux helpers ----
__device__ __forceinline__ double pack2(float lo, float hi) {
    double d; asm("mov.b64 %0, {%1, %2};" : "=d"(d) : "f"(lo), "f"(hi)); return d;
}
__device__ __forceinline__ double fma2(double a, double b, double c) {
    double d; asm("fma.rn.f32x2 %0, %1, %2, %3;" : "=d"(d) : "d"(a), "d"(b), "d"(c)); return d;
}
__device__ __forceinline__ double add2(double a, double b) {
    double d; asm("add.rn.f32x2 %0, %1, %2;" : "=d"(d) : "d"(a), "d"(b)); return d;
}
__device__ __forceinline__ void unpack2(double d, float& lo, float& hi) {
    asm("mov.b64 {%0, %1}, %2;" : "=f"(lo), "=f"(hi) : "d"(d));
}
__device__ __forceinline__ void lds_v2b64(double& a, double& b, unsigned addr) {
    asm volatile("ld.shared.v2.b64 {%0, %1}, [%2];" : "=d"(a), "=d"(b) : "r"(addr));
}
__device__ __forceinline__ unsigned redux_min_u32(unsigned v) {
    unsigned r; asm("redux.sync.min.u32 %0, %1, 0xffffffff;" : "=r"(r) : "r"(v)); return r;
}

// Stage 1 (hot loop identical to R13-R15 — measured 30.1us): block =
// (b, i-chunk of 512, j-segment of 128).
//   d''' = (-2qx)tx + (-2qy)ty + (-2qz)tz + ((t^2+128) + q^2)  ( > 0 )
// Col mins buffer in SMEM per warp, fold across warps post-loop, then ONE
// atomicMax(~bits) per (block, j). Row mins: 4 atomicMax(~bits) per thread.
// Max of complemented positive-float bits == float min; order-independent
// -> deterministic, and the identity element is 0 (no init kernel needed).
__global__ __launch_bounds__(THREADS, 5)
void chamfer_stage1(const float* __restrict__ x, const float* __restrict__ y) {
    __shared__ __align__(16) float sm[4 * JSEG];    // tx, ty, tz, t^2+BIAS
    __shared__ __align__(16) float scol[4 * JSEG];  // per-warp col mins

    const int blk = blockIdx.x;
    const int jh  = blk & 31;
    const int ic  = (blk >> 5) & 7;
    const int b   = blk >> 8;

    const float* __restrict__ q = x + b * NPTS * 3;
    const float* __restrict__ t = y + b * NPTS * 3;
    const int j0 = jh * JSEG;

    if (threadIdx.x < JSEG) {
        const int i = threadIdx.x;
        const float tx = t[(j0 + i) * 3 + 0];
        const float ty = t[(j0 + i) * 3 + 1];
        const float tz = t[(j0 + i) * 3 + 2];
        sm[i] = tx; sm[JSEG + i] = ty; sm[2 * JSEG + i] = tz;
        sm[3 * JSEG + i] = tx * tx + ty * ty + tz * tz + BIAS;
    }
    __syncthreads();

    // 4 queries per thread: i = ic*512 + tid + {0,128,256,384}
    double px[NQ], py[NQ], pz[NQ], ps[NQ];
    int ibase = ic * 512 + threadIdx.x;
#pragma unroll
    for (int qi = 0; qi < NQ; qi++) {
        const int i = ibase + qi * THREADS;
        const float qx = q[i * 3 + 0], qy = q[i * 3 + 1], qz = q[i * 3 + 2];
        px[qi] = pack2(-2.f * qx, -2.f * qx);
        py[qi] = pack2(-2.f * qy, -2.f * qy);
        pz[qi] = pack2(-2.f * qz, -2.f * qz);
        const float qs = qx * qx + qy * qy + qz * qz;
        ps[qi] = pack2(qs, qs);
    }

    float r0[NQ], r1[NQ];
#pragma unroll
    for (int qi = 0; qi < NQ; qi++) { r0[qi] = 1e30f; r1[qi] = 1e30f; }

    const int wid = threadIdx.x >> 5;
    const bool lane0 = (threadIdx.x & 31) == 0;
    float4* __restrict__ colbuf = (float4*)&scol[wid * JSEG];

    unsigned a = (unsigned)__cvta_generic_to_shared(sm);

#pragma unroll 4
    for (int k = 0; k < JSEG / 4; k++, a += 16) {
        double x01, x23, y01, y23, z01, z23, w01, w23;
        lds_v2b64(x01, x23, a);
        lds_v2b64(y01, y23, a + 512u);
        lds_v2b64(z01, z23, a + 1024u);
        lds_v2b64(w01, w23, a + 1536u);

        float f0[NQ], f1[NQ], f2[NQ], f3[NQ];
#pragma unroll
        for (int qi = 0; qi < NQ; qi++) {
            const double t01 = add2(w01, ps[qi]);
            const double t23 = add2(w23, ps[qi]);
            const double d0 =
                fma2(px[qi], x01, fma2(py[qi], y01, fma2(pz[qi], z01, t01)));
            const double d1 =
                fma2(px[qi], x23, fma2(py[qi], y23, fma2(pz[qi], z23, t23)));
            unpack2(d0, f0[qi], f1[qi]);
            unpack2(d1, f2[qi], f3[qi]);
            r0[qi] = fminf(fminf(r0[qi], f0[qi]), f2[qi]);
            r1[qi] = fminf(fminf(r1[qi], f1[qi]), f3[qi]);
        }

        // col fold across the 4 queries, then across the warp's 32 lanes
        const float c0 = fminf(fminf(f0[0], f0[1]), fminf(f0[2], f0[3]));
        const float c1 = fminf(fminf(f1[0], f1[1]), fminf(f1[2], f1[3]));
        const float c2 = fminf(fminf(f2[0], f2[1]), fminf(f2[2], f2[3]));
        const float c3 = fminf(fminf(f3[0], f3[1]), fminf(f3[2], f3[3]));
        const unsigned u0 = redux_min_u32(__float_as_uint(c0));
        const unsigned u1 = redux_min_u32(__float_as_uint(c1));
        const unsigned u2 = redux_min_u32(__float_as_uint(c2));
        const unsigned u3 = redux_min_u32(__float_as_uint(c3));
        if (lane0)
            colbuf[k] = make_float4(__uint_as_float(u0), __uint_as_float(u1),
                                    __uint_as_float(u2), __uint_as_float(u3));
    }

    // row mins -> global atomic max of ~bits (order-independent, exact)
#pragma unroll
    for (int qi = 0; qi < NQ; qi++) {
        const int i = ibase + qi * THREADS;
        atomicMax(&g_rowmin[b * NPTS + i],
                  ~__float_as_uint(fminf(r0[qi], r1[qi])));
    }

    // fold 4 warp-col buffers and issue one atomic max per j
    __syncthreads();
    {
        const int j = threadIdx.x;           // 0..127
        const float m = fminf(fminf(scol[j], scol[JSEG + j]),
                              fminf(scol[2 * JSEG + j], scol[3 * JSEG + j]));
        atomicMax(&g_colmin[b * NPTS + j0 + j], ~__float_as_uint(m));
    }
}

// Stage 2: 64 blocks sum the 64K mins (complemented bits -> float, unbias),
// zero the slots they read (state reset for the next invocation), and
// accumulate into a fixed-point u64 (integer add = associative =
// deterministic). The last block converts and writes the scalar, then
// resets g_acc/g_ticket.
__global__ __launch_bounds__(256)
void chamfer_stage2(float* __restrict__ out) {
    unsigned* src = (blockIdx.x < 32) ? g_colmin : g_rowmin;
    const int idx = (blockIdx.x & 31) * 256 + threadIdx.x;
    const uint4 v = ((const uint4*)src)[idx];
    ((uint4*)src)[idx] = make_uint4(0u, 0u, 0u, 0u);   // reset for next call
    float local = (__uint_as_float(~v.x) - BIAS) + (__uint_as_float(~v.y) - BIAS)
                + (__uint_as_float(~v.z) - BIAS) + (__uint_as_float(~v.w) - BIAS);
    __shared__ float red[8];
#pragma unroll
    for (int o = 16; o; o >>= 1) local += __shfl_down_sync(0xFFFFFFFFu, local, o);
    if ((threadIdx.x & 31) == 0) red[threadIdx.x >> 5] = local;
    __syncthreads();
    if (threadIdx.x == 0) {
        const float s = ((red[0] + red[1]) + (red[2] + red[3]))
                      + ((red[4] + red[5]) + (red[6] + red[7]));
        atomicAdd(&g_acc, (unsigned long long)((double)s * SCALE + 0.5));
        __threadfence();
        const unsigned t = atomicAdd(&g_ticket, 1u);
        if (t == 63u) {
            const unsigned long long acc = atomicAdd(&g_acc, 0ULL);
            out[0] = (float)((double)acc * (1.0 / SCALE) * (0.005 / 32768.0));
            g_acc = 0ULL;          // reset for next invocation
            g_ticket = 0u;
            __threadfence();
        }
    }
}

extern "C" void kernel_launch(void* const* d_in, const int* in_sizes, int n_in,
                              void* d_out, int out_size) {
    const float* x = (const float*)d_in[0];
    const float* y = (const float*)d_in[1];
    float* out = (float*)d_out;
    chamfer_stage1<<<NB * NIC * NJH, THREADS>>>(x, y);
    chamfer_stage2<<<64, 256>>>(out);
}